// round 4
// baseline (speedup 1.0000x reference)
#include <cuda_runtime.h>
#include <cstdint>

// Fixed problem shape (setup_inputs)
#define BATCH   16
#define CIN     64
#define HH      224
#define WW      224
#define COUT    64
#define PH      64
#define PW      64

#define TILE_I  32
#define GROUP   2
#define SM_ROWS 34
#define SM_COLS 66
#define PLANE_N (SM_ROWS*SM_COLS)     // 2244
#define PLANES  2                     // input channels per stage
#define NTHREADS 256

#define COPY_BLOCKS 512
#define CONV_BLOCKS 1024              // 2 tiles * 32 cogroups * 16 batches
#define TOTAL_BLOCKS (COPY_BLOCKS + CONV_BLOCKS)

// copy geometry: 16*64*224*224/4 = 12,845,056 float4; 512*256 threads -> 98 each
#define GSTRIDE    131072u
#define COPY_PER_T 98

// ---------------- PTX helpers ----------------
__device__ __forceinline__ void cp_async4(uint32_t s, const float* g) {
    asm volatile("cp.async.ca.shared.global [%0], [%1], 4;\n" :: "r"(s), "l"(g));
}
__device__ __forceinline__ void cp_commit() {
    asm volatile("cp.async.commit_group;\n" ::);
}
template<int N> __device__ __forceinline__ void cp_wait() {
    asm volatile("cp.async.wait_group %0;\n" :: "n"(N));
}
__device__ __forceinline__ uint64_t pack2(float lo, float hi) {
    uint64_t r; asm("mov.b64 %0, {%1, %2};" : "=l"(r) : "f"(lo), "f"(hi)); return r;
}
__device__ __forceinline__ void unpack2(uint64_t v, float& lo, float& hi) {
    asm("mov.b64 {%0, %1}, %2;" : "=f"(lo), "=f"(hi) : "l"(v));
}
__device__ __forceinline__ void fma2(uint64_t& d, uint64_t a, uint64_t b) {
    asm("fma.rn.f32x2 %0, %1, %2, %0;" : "+l"(d) : "l"(a), "l"(b));
}

__global__ __launch_bounds__(256, 3)
void inc_conv_kernel(const float* __restrict__ in,
                     const float* __restrict__ wgt,
                     const float* __restrict__ bias,
                     const float* __restrict__ outsrc,
                     float* __restrict__ out,
                     const int* __restrict__ p_pad,
                     const int* __restrict__ p_prs,
                     const int* __restrict__ p_pcs)
{
    const int tid = threadIdx.x;
    const int bid = blockIdx.x;
    const int prs = *p_prs;
    const int pcs = *p_pcs;

    // ================= COPY BLOCKS =================
    if (bid < COPY_BLOCKS) {
        const unsigned gthr = (unsigned)bid * NTHREADS + (unsigned)tid;
        for (int k = 0; k < COPY_PER_T; k++) {
            unsigned i4 = gthr + (unsigned)k * GSTRIDE;
            unsigned rem = i4 % 12544u;            // within one 224x224 plane (f4)
            unsigned h = rem / 56u;
            unsigned wcol = (rem - h * 56u) * 4u;
            bool in_rows = (h >= (unsigned)prs) && (h < (unsigned)(prs + PH));
            bool full_in = in_rows && wcol >= (unsigned)pcs &&
                           (wcol + 4u) <= (unsigned)(pcs + PW);
            if (full_in) continue;
            float4 v = __ldg(((const float4*)outsrc) + i4);
            bool overlap = in_rows && (wcol + 3u >= (unsigned)pcs) &&
                           (wcol < (unsigned)(pcs + PW));
            if (!overlap) {
                ((float4*)out)[i4] = v;
            } else {
                const float* vf = (const float*)&v;
#pragma unroll
                for (int e = 0; e < 4; e++) {
                    unsigned wc = wcol + e;
                    if (wc < (unsigned)pcs || wc >= (unsigned)(pcs + PW))
                        out[(size_t)i4 * 4 + e] = vf[e];
                }
            }
        }
        return;
    }

    // ================= CONV BLOCKS =================
    const int padding = *p_pad;
    const int cid  = bid - COPY_BLOCKS;
    const int tile = cid & 1;
    const int cog  = (cid >> 1) & 31;
    const int b    = cid >> 6;
    const int co0  = cog * GROUP;
    const int tile_i = tile * TILE_I;

    const int tx = tid & 63;
    const int ty = tid >> 6;
    const int ibr = ty * 8;          // first tile-row this thread owns

    __shared__ float  s_in[2][PLANES * PLANE_N];
    __shared__ float2 s_wp[GROUP][CIN][9];

    // stage duplicated weights (GROUP*64*9 = 1152)
    for (int idx = tid; idx < GROUP * CIN * 9; idx += NTHREADS) {
        int g = idx / (CIN * 9);
        int rem = idx % (CIN * 9);
        float w = wgt[(size_t)(co0 + g) * (CIN * 9) + rem];
        s_wp[g][rem / 9][rem % 9] = make_float2(w, w);
    }

    const int row0 = prs + tile_i - padding;
    const int col0 = pcs - padding;
    const float* inb = in + (size_t)b * CIN * HH * WW;

    uint32_t sbase[2];
    sbase[0] = (uint32_t)__cvta_generic_to_shared(&s_in[0][0]);
    sbase[1] = (uint32_t)__cvta_generic_to_shared(&s_in[1][0]);

    // staging coordinates (rolled, avoids div in loop)
    const int st_r0 = tid / SM_COLS;
    const int st_c0 = tid - st_r0 * SM_COLS;

    // stage 'PLANES' consecutive ci planes into buffer `buf`, first plane = ci0
    auto stage2 = [&](int buf, int ci0) {
#pragma unroll
        for (int pl = 0; pl < PLANES; pl++) {
            const float* inc = inb + (size_t)(ci0 + pl) * (HH * WW);
            uint32_t sb = sbase[buf] + (uint32_t)(pl * PLANE_N) * 4u;
            int r = st_r0, c = st_c0, idx = tid;
#pragma unroll
            for (int j = 0; j < 9; j++) {
                if (idx < PLANE_N) {
                    int gr = row0 + r, gc = col0 + c;
                    uint32_t sa = sb + (uint32_t)idx * 4u;
                    if ((unsigned)gr < (unsigned)HH && (unsigned)gc < (unsigned)WW) {
                        cp_async4(sa, inc + gr * WW + gc);
                    } else {
                        unsigned z = 0;
                        asm volatile("st.shared.b32 [%0], %1;\n" :: "r"(sa), "r"(z));
                    }
                }
                idx += NTHREADS;
                r += 3; c += 58;
                if (c >= SM_COLS) { c -= SM_COLS; r += 1; }
            }
        }
        cp_commit();
    };

    // accumulators: GROUP couts x 4 row-pairs
    uint64_t acc[GROUP][4];
#pragma unroll
    for (int g = 0; g < GROUP; g++) {
        float bz = bias[co0 + g];
        uint64_t pb = pack2(bz, bz);
#pragma unroll
        for (int p = 0; p < 4; p++) acc[g][p] = pb;
    }

    stage2(0, 0);   // prologue

    const int NITER = CIN / PLANES;   // 32
    for (int it = 0; it < NITER; it++) {
        if (it + 1 < NITER) {
            stage2((it + 1) & 1, (it + 1) * PLANES);
            cp_wait<1>();
        } else {
            cp_wait<0>();
        }
        __syncthreads();

        const float* Sbuf = s_in[it & 1];
#pragma unroll
        for (int pl = 0; pl < PLANES; pl++) {
            const int ci = it * PLANES + pl;
            const float* S = Sbuf + pl * PLANE_N;

#pragma unroll
            for (int g = 0; g < GROUP; g++) {
                const uint64_t* wp =
                    reinterpret_cast<const uint64_t*>(&s_wp[g][ci][0]);
                uint64_t w[9];
#pragma unroll
                for (int k = 0; k < 9; k++) w[k] = wp[k];

                // rolling 2-row window; pairs pAB=(r,r+1), pBC, pCD
                float a0 = S[(ibr + 0) * SM_COLS + tx];
                float a1 = S[(ibr + 0) * SM_COLS + tx + 1];
                float a2 = S[(ibr + 0) * SM_COLS + tx + 2];
                float b0 = S[(ibr + 1) * SM_COLS + tx];
                float b1 = S[(ibr + 1) * SM_COLS + tx + 1];
                float b2 = S[(ibr + 1) * SM_COLS + tx + 2];
                uint64_t pAB0 = pack2(a0, b0);
                uint64_t pAB1 = pack2(a1, b1);
                uint64_t pAB2 = pack2(a2, b2);

#pragma unroll
                for (int p = 0; p < 4; p++) {
                    int r2 = ibr + 2 * p + 2;
                    float c0 = S[r2 * SM_COLS + tx];
                    float c1 = S[r2 * SM_COLS + tx + 1];
                    float c2 = S[r2 * SM_COLS + tx + 2];
                    float d0 = S[(r2 + 1) * SM_COLS + tx];
                    float d1 = S[(r2 + 1) * SM_COLS + tx + 1];
                    float d2 = S[(r2 + 1) * SM_COLS + tx + 2];

                    uint64_t pBC0 = pack2(b0, c0);
                    uint64_t pBC1 = pack2(b1, c1);
                    uint64_t pBC2 = pack2(b2, c2);
                    uint64_t pCD0 = pack2(c0, d0);
                    uint64_t pCD1 = pack2(c1, d1);
                    uint64_t pCD2 = pack2(c2, d2);

                    fma2(acc[g][p], pAB0, w[0]);
                    fma2(acc[g][p], pAB1, w[1]);
                    fma2(acc[g][p], pAB2, w[2]);
                    fma2(acc[g][p], pBC0, w[3]);
                    fma2(acc[g][p], pBC1, w[4]);
                    fma2(acc[g][p], pBC2, w[5]);
                    fma2(acc[g][p], pCD0, w[6]);
                    fma2(acc[g][p], pCD1, w[7]);
                    fma2(acc[g][p], pCD2, w[8]);

                    // roll down two rows
                    b0 = d0; b1 = d1; b2 = d2;
                    pAB0 = pCD0; pAB1 = pCD1; pAB2 = pCD2;
                }
            }
        }
        __syncthreads();   // all reads done before this buffer is re-staged
    }

    // ---------- epilogue: write the patch ----------
#pragma unroll
    for (int g = 0; g < GROUP; g++) {
        float* outc = out + ((size_t)b * COUT + (co0 + g)) * HH * WW;
#pragma unroll
        for (int p = 0; p < 4; p++) {
            float lo, hi;
            unpack2(acc[g][p], lo, hi);
            int orow = prs + tile_i + ibr + 2 * p;
            int ocol = pcs + tx;
            outc[(size_t)orow * WW + ocol] = lo;
            outc[(size_t)(orow + 1) * WW + ocol] = hi;
        }
    }
}

extern "C" void kernel_launch(void* const* d_in, const int* in_sizes, int n_in,
                              void* d_out, int out_size) {
    const float* in_tensor = (const float*)d_in[0];
    const float* weights   = (const float*)d_in[1];
    const float* biases    = (const float*)d_in[2];
    const float* out_base  = (const float*)d_in[3];
    const int*   p_pad     = (const int*)d_in[4];
    const int*   p_prs     = (const int*)d_in[7];
    const int*   p_pcs     = (const int*)d_in[8];

    inc_conv_kernel<<<TOTAL_BLOCKS, NTHREADS>>>(
        in_tensor, weights, biases, out_base, (float*)d_out,
        p_pad, p_prs, p_pcs);
}

// round 5
// speedup vs baseline: 1.8467x; 1.8467x over previous
#include <cuda_runtime.h>
#include <cstdint>

// Fixed problem shape (setup_inputs)
#define BATCH   16
#define CIN     64
#define HH      224
#define WW      224
#define COUT    64
#define PH      64
#define PW      64

#define NT       256
#define TILE_I   8                      // output rows per conv block
#define SM_ROWS  10                     // TILE_I + 2
#define SM_COLS  72                     // 18 float4, covers 66-col window + align slack
#define SM_C4    (SM_COLS/4)            // 18
#define PLANE_F4 (SM_ROWS*SM_C4)        // 180
#define PLANE_N  (SM_ROWS*SM_COLS)      // 720
#define PLANES   2                      // input channels per stage

#define CONV_BLOCKS 1024                // 8 rowtiles * 8 cogroups * 16 batch
#define COPY_BLOCKS 1024
#define TOTAL_BLOCKS 2048

// copy: 16*64*224*224/4 = 12,845,056 float4 = 1024*256*49 exactly
#define COPY_STRIDE 262144u
#define COPY_PER_T  49

// ---------------- PTX helpers ----------------
__device__ __forceinline__ void cp_async16(uint32_t s, const float* g) {
    asm volatile("cp.async.cg.shared.global [%0], [%1], 16;\n" :: "r"(s), "l"(g));
}
__device__ __forceinline__ void cp_commit() {
    asm volatile("cp.async.commit_group;\n" ::);
}
template<int N> __device__ __forceinline__ void cp_wait() {
    asm volatile("cp.async.wait_group %0;\n" :: "n"(N));
}
__device__ __forceinline__ uint64_t pack2(float lo, float hi) {
    uint64_t r; asm("mov.b64 %0, {%1, %2};" : "=l"(r) : "f"(lo), "f"(hi)); return r;
}
__device__ __forceinline__ uint64_t dup2(float v) {
    uint64_t r; asm("mov.b64 %0, {%1, %1};" : "=l"(r) : "f"(v)); return r;
}
__device__ __forceinline__ void unpack2(uint64_t v, float& lo, float& hi) {
    asm("mov.b64 {%0, %1}, %2;" : "=f"(lo), "=f"(hi) : "l"(v));
}
__device__ __forceinline__ void fma2(uint64_t& d, uint64_t a, uint64_t b) {
    asm("fma.rn.f32x2 %0, %1, %2, %0;" : "+l"(d) : "l"(a), "l"(b));
}

__global__ __launch_bounds__(256, 3)
void inc_conv_kernel(const float* __restrict__ in,
                     const float* __restrict__ wgt,
                     const float* __restrict__ bias,
                     const float* __restrict__ outsrc,
                     float* __restrict__ out,
                     const int* __restrict__ p_pad,
                     const int* __restrict__ p_prs,
                     const int* __restrict__ p_pcs)
{
    const int tid = threadIdx.x;
    const int bid = blockIdx.x;
    const int prs = *p_prs;
    const int pcs = *p_pcs;

    // ================= COPY BLOCKS (odd bid) =================
    if (bid & 1) {
        const unsigned cid  = (unsigned)bid >> 1;
        const unsigned gthr = cid * NT + (unsigned)tid;
#pragma unroll 4
        for (int k = 0; k < COPY_PER_T; k++) {
            unsigned i4 = gthr + (unsigned)k * COPY_STRIDE;
            unsigned rem = i4 % 12544u;            // within one 224x224 plane (f4)
            unsigned h = rem / 56u;
            unsigned wcol = (rem - h * 56u) * 4u;
            bool in_rows = (h >= (unsigned)prs) && (h < (unsigned)(prs + PH));
            bool full_in = in_rows && wcol >= (unsigned)pcs &&
                           (wcol + 4u) <= (unsigned)(pcs + PW);
            if (full_in) continue;
            float4 v = __ldg(((const float4*)outsrc) + i4);
            bool overlap = in_rows && (wcol + 3u >= (unsigned)pcs) &&
                           (wcol < (unsigned)(pcs + PW));
            if (!overlap) {
                ((float4*)out)[i4] = v;
            } else {
                const float* vf = (const float*)&v;
#pragma unroll
                for (int e = 0; e < 4; e++) {
                    unsigned wc = wcol + e;
                    if (wc < (unsigned)pcs || wc >= (unsigned)(pcs + PW))
                        out[(size_t)i4 * 4 + e] = vf[e];
                }
            }
        }
        return;
    }

    // ================= CONV BLOCKS (even bid) =================
    const int padding = *p_pad;
    const int cid = bid >> 1;            // 0..1023
    const int rt  = cid & 7;             // row tile (8 rows each)
    const int cog = (cid >> 3) & 7;      // cout group (8 couts)
    const int b   = cid >> 6;            // batch
    const int co0 = cog * 8;

    const int tx  = tid & 63;            // output col
    const int ty  = tid >> 6;            // 0..3
    const int ibr = ty * 2;              // first output row (tile-local)

    __shared__ float    s_in[2][PLANES * PLANE_N];
    __shared__ uint64_t s_wp[4][CIN][9]; // cout-pair packed weights

    // stage packed weights: 4 pairs * 64 ci * 9 taps
    for (int idx = tid; idx < 4 * CIN * 9; idx += NT) {
        int p   = idx / (CIN * 9);
        int rem = idx % (CIN * 9);
        float w0 = wgt[(size_t)(co0 + 2 * p) * (CIN * 9) + rem];
        float w1 = wgt[(size_t)(co0 + 2 * p + 1) * (CIN * 9) + rem];
        s_wp[p][rem / 9][rem % 9] = pack2(w0, w1);
    }

    const int row0  = prs + rt * TILE_I - padding;
    const int col0a = ((pcs - padding) >= 0) ? ((pcs - padding) & ~3)
                                             : -((4 - ((pcs - padding) & 3)) & 3) + (pcs - padding) - ((pcs - padding) & 3);
    const int coff  = (pcs - padding) - col0a;   // 0..3
    const float* inb = in + (size_t)b * CIN * HH * WW;

    uint32_t sbase[2];
    sbase[0] = (uint32_t)__cvta_generic_to_shared(&s_in[0][0]);
    sbase[1] = (uint32_t)__cvta_generic_to_shared(&s_in[1][0]);

    // stage PLANES consecutive ci planes into buffer buf (first plane ci0)
    auto stage = [&](int buf, int ci0) {
#pragma unroll
        for (int j = 0; j < 2; j++) {
            int idx = tid + j * NT;
            if (idx < PLANES * PLANE_F4) {
                int pl  = idx / PLANE_F4;
                int rem = idx - pl * PLANE_F4;
                int r   = rem / SM_C4;
                int c4  = rem - r * SM_C4;
                int gr  = row0 + r;
                int gc  = col0a + c4 * 4;
                uint32_t sa = sbase[buf] +
                    (uint32_t)(pl * PLANE_N + r * SM_COLS + c4 * 4) * 4u;
                const float* gp = inb + (size_t)(ci0 + pl) * (HH * WW)
                                  + (size_t)gr * WW + gc;
                if ((unsigned)gr < (unsigned)HH && gc >= 0 && gc + 3 < WW) {
                    cp_async16(sa, gp);
                } else {
                    float v0 = 0, v1 = 0, v2 = 0, v3 = 0;
                    if ((unsigned)gr < (unsigned)HH) {
                        if ((unsigned)(gc + 0) < (unsigned)WW) v0 = gp[0];
                        if ((unsigned)(gc + 1) < (unsigned)WW) v1 = gp[1];
                        if ((unsigned)(gc + 2) < (unsigned)WW) v2 = gp[2];
                        if ((unsigned)(gc + 3) < (unsigned)WW) v3 = gp[3];
                    }
                    asm volatile("st.shared.v4.b32 [%0], {%1,%2,%3,%4};\n"
                                 :: "r"(sa), "f"(v0), "f"(v1), "f"(v2), "f"(v3));
                }
            }
        }
        cp_commit();
    };

    // accumulators: 4 cout-pairs x 2 rows
    uint64_t acc[4][2];
#pragma unroll
    for (int p = 0; p < 4; p++) {
        uint64_t pb = pack2(bias[co0 + 2 * p], bias[co0 + 2 * p + 1]);
        acc[p][0] = pb; acc[p][1] = pb;
    }

    stage(0, 0);   // prologue

    const int NITER = CIN / PLANES;   // 32
    for (int it = 0; it < NITER; it++) {
        if (it + 1 < NITER) {
            stage((it + 1) & 1, (it + 1) * PLANES);
            cp_wait<1>();
        } else {
            cp_wait<0>();
        }
        __syncthreads();

        const float* Sbuf = s_in[it & 1];
#pragma unroll
        for (int pl = 0; pl < PLANES; pl++) {
            const int ci = it * PLANES + pl;
            const float* S = Sbuf + pl * PLANE_N + (ibr * SM_COLS) + tx + coff;

            // 4 input rows x 3 cols, duplicated into both lanes
            uint64_t x[4][3];
#pragma unroll
            for (int r = 0; r < 4; r++)
#pragma unroll
                for (int c = 0; c < 3; c++)
                    x[r][c] = dup2(S[r * SM_COLS + c]);

#pragma unroll
            for (int p = 0; p < 4; p++) {
                const uint64_t* wp = &s_wp[p][ci][0];
                uint64_t w[9];
#pragma unroll
                for (int k = 0; k < 9; k++) w[k] = wp[k];

                fma2(acc[p][0], x[0][0], w[0]);
                fma2(acc[p][0], x[0][1], w[1]);
                fma2(acc[p][0], x[0][2], w[2]);
                fma2(acc[p][0], x[1][0], w[3]);
                fma2(acc[p][0], x[1][1], w[4]);
                fma2(acc[p][0], x[1][2], w[5]);
                fma2(acc[p][0], x[2][0], w[6]);
                fma2(acc[p][0], x[2][1], w[7]);
                fma2(acc[p][0], x[2][2], w[8]);

                fma2(acc[p][1], x[1][0], w[0]);
                fma2(acc[p][1], x[1][1], w[1]);
                fma2(acc[p][1], x[1][2], w[2]);
                fma2(acc[p][1], x[2][0], w[3]);
                fma2(acc[p][1], x[2][1], w[4]);
                fma2(acc[p][1], x[2][2], w[5]);
                fma2(acc[p][1], x[3][0], w[6]);
                fma2(acc[p][1], x[3][1], w[7]);
                fma2(acc[p][1], x[3][2], w[8]);
            }
        }
        __syncthreads();   // all reads done before this buffer is re-staged
    }

    // ---------- epilogue: write the patch (coalesced along tx) ----------
#pragma unroll
    for (int p = 0; p < 4; p++) {
#pragma unroll
        for (int r = 0; r < 2; r++) {
            float lo, hi;
            unpack2(acc[p][r], lo, hi);
            int orow = prs + rt * TILE_I + ibr + r;
            int ocol = pcs + tx;
            size_t base = (size_t)orow * WW + ocol;
            out[((size_t)b * COUT + (co0 + 2 * p)) * (HH * WW) + base] = lo;
            out[((size_t)b * COUT + (co0 + 2 * p + 1)) * (HH * WW) + base] = hi;
        }
    }
}

extern "C" void kernel_launch(void* const* d_in, const int* in_sizes, int n_in,
                              void* d_out, int out_size) {
    const float* in_tensor = (const float*)d_in[0];
    const float* weights   = (const float*)d_in[1];
    const float* biases    = (const float*)d_in[2];
    const float* out_base  = (const float*)d_in[3];
    const int*   p_pad     = (const int*)d_in[4];
    const int*   p_prs     = (const int*)d_in[7];
    const int*   p_pcs     = (const int*)d_in[8];

    inc_conv_kernel<<<TOTAL_BLOCKS, NT>>>(
        in_tensor, weights, biases, out_base, (float*)d_out,
        p_pad, p_prs, p_pcs);
}